// round 9
// baseline (speedup 1.0000x reference)
#include <cuda_runtime.h>
#include <cuda_bf16.h>
#include <cstdint>

#define HID     32
#define TILE_M  128
#define THREADS 256
#define BSTRIDE 136                  // padded bf16 per B row (272B): conflict-free ldmatrix
#define BHALF   (64 * BSTRIDE)       // elements per version (hi/lo)

// Fused W^T, split bf16, gate-interleaved rows:
// storage row n: block b=n>>3 (0..7), i=n&7; gate=b&1 (0:z,1:h); col j=(b>>1)*8+i.
// So rows [0..31] hold z0-7,h0-7,z8-15,h8-15 (n-half 0), rows [32..63] j=16..31 (n-half 1).
__device__ __align__(16) __nv_bfloat16 g_B[2 * BHALF];

// W tensors shape (2,1,160,32); [s,0,k,j] = s*5120 + k*32 + j; only k<128 live (H0=0).
__global__ void prep_kernel(const float* __restrict__ Wz, const float* __restrict__ Wh) {
    int idx = blockIdx.x * blockDim.x + threadIdx.x;   // 0..8191
    if (idx >= 64 * 128) return;
    int n = idx >> 7;
    int k = idx & 127;
    int b = n >> 3;
    int i = n & 7;
    int j = (b >> 1) * 8 + i;
    const float* W = (b & 1) ? Wh : Wz;
    float v = W[k * 32 + j] + W[5120 + k * 32 + j];
    __nv_bfloat16 hi = __float2bfloat16_rn(v);
    float lo = v - __bfloat162float(hi);
    g_B[n * BSTRIDE + k]         = hi;
    g_B[BHALF + n * BSTRIDE + k] = __float2bfloat16_rn(lo);
}

// ---------------- helpers ----------------
__device__ __forceinline__ uint32_t smem_u32(const void* p) {
    uint32_t a;
    asm("{ .reg .u64 t; cvta.to.shared.u64 t, %1; cvt.u32.u64 %0, t; }" : "=r"(a) : "l"(p));
    return a;
}
__device__ __forceinline__ void mma_bf16(float* d, const uint32_t* a, const uint32_t* b) {
    asm volatile(
        "mma.sync.aligned.m16n8k16.row.col.f32.bf16.bf16.f32 "
        "{%0,%1,%2,%3}, {%4,%5,%6,%7}, {%8,%9}, {%0,%1,%2,%3};"
        : "+f"(d[0]), "+f"(d[1]), "+f"(d[2]), "+f"(d[3])
        : "r"(a[0]), "r"(a[1]), "r"(a[2]), "r"(a[3]), "r"(b[0]), "r"(b[1]));
}
__device__ __forceinline__ void ldm_x4(uint32_t* r, uint32_t addr) {
    asm volatile("ldmatrix.sync.aligned.m8n8.x4.shared.b16 {%0,%1,%2,%3}, [%4];"
        : "=r"(r[0]), "=r"(r[1]), "=r"(r[2]), "=r"(r[3]) : "r"(addr));
}
__device__ __forceinline__ uint32_t pack_bf2(float a, float b) {
    __nv_bfloat162 t = __floats2bfloat162_rn(a, b);
    return *(uint32_t*)&t;
}
__device__ __forceinline__ float sigmoid_f(float v) {
    return __fdividef(1.0f, 1.0f + __expf(-v));
}
__device__ __forceinline__ float tanh_f(float v) {
    return 1.0f - __fdividef(2.0f, __expf(2.0f * v) + 1.0f);
}

__global__ void __launch_bounds__(THREADS, 3)
dcrnn_mma_kernel(const float* __restrict__ x,
                 const float* __restrict__ bz, const float* __restrict__ bh,
                 const float* __restrict__ wlin, const float* __restrict__ blin,
                 float* __restrict__ out, int nNodes)
{
    __shared__ __align__(16) __nv_bfloat16 sB[2 * BHALF];   // 34816 B
    __shared__ float sRed[2][TILE_M];                       // 1 KB

    const int tid = threadIdx.x;

    // stage B (hi+lo) -> smem, 2176 uint4
    {
        const uint4* src = (const uint4*)g_B;
        uint4*       dst = (uint4*)sB;
        #pragma unroll
        for (int i = 0; i < 2176 / THREADS + 1; i++) {
            int e = tid + i * THREADS;
            if (e < 2176) dst[e] = src[e];
        }
    }
    __syncthreads();

    const int warp   = tid >> 5;
    const int mstrip = warp & 3;       // 32-row strip
    const int nhalf  = warp >> 2;      // B row half (gate-col pairs j: nhalf*16..+16)
    const int lane   = tid & 31;
    const int g      = lane >> 2;      // 0..7
    const int c      = lane & 3;       // 0..3
    const int rowBase = blockIdx.x * TILE_M + mstrip * 32;

    // 4 x-row pointers (rows g, g+8, g+16, g+24), clamped for loads
    const float* rowp[4];
    #pragma unroll
    for (int r = 0; r < 4; r++) {
        int rr = rowBase + g + 8 * r;
        if (rr >= nNodes) rr = nNodes - 1;
        rowp[r] = x + (size_t)rr * 128 + 2 * c;
    }

    // B ldmatrix per-thread address: within a 16-row n-tile pair,
    // tgrp = lane>>3: 0:(row=trow,kb0) 1:(row=trow,kb1) 2:(row=8+trow,kb0) 3:(row=8+trow,kb1)
    const uint32_t sB0 = smem_u32(sB);
    const uint32_t tb  = (uint32_t)((((lane >> 4) << 3) + (lane & 7)) * (BSTRIDE * 2)
                                    + ((lane >> 3) & 1) * 16);
    const uint32_t bbase = sB0 + (uint32_t)(nhalf * 32 * BSTRIDE * 2) + tb;

    // acc[mt][nt][e]: nt even = z block, nt odd = h block (same cols)
    float acc[2][4][4];
    #pragma unroll
    for (int mt = 0; mt < 2; mt++)
        #pragma unroll
        for (int nt = 0; nt < 4; nt++)
            #pragma unroll
            for (int e = 0; e < 4; e++) acc[mt][nt][e] = 0.0f;

    #pragma unroll 2
    for (int kt = 0; kt < 8; kt++) {
        // A fragments straight from gmem: 8x LDG.64 (f32 pairs), split hi/lo in regs
        float2 av[4][2];
        #pragma unroll
        for (int r = 0; r < 4; r++) {
            av[r][0] = *(const float2*)(rowp[r] + kt * 16);
            av[r][1] = *(const float2*)(rowp[r] + kt * 16 + 8);
        }
        uint32_t Ah[2][4], Al[2][4];
        #pragma unroll
        for (int mt = 0; mt < 2; mt++)
            #pragma unroll
            for (int kb = 0; kb < 2; kb++)
                #pragma unroll
                for (int rr = 0; rr < 2; rr++) {
                    float2 v = av[mt * 2 + rr][kb];
                    __nv_bfloat162 h2 = __floats2bfloat162_rn(v.x, v.y);
                    float lx = v.x - __bfloat162float(h2.x);
                    float ly = v.y - __bfloat162float(h2.y);
                    Ah[mt][kb * 2 + rr] = *(uint32_t*)&h2;
                    Al[mt][kb * 2 + rr] = pack_bf2(lx, ly);
                }

        // B hi fragments: 2x ldmatrix.x4 covering this warp's 4 n-tiles
        uint32_t B2[4][2];
        #pragma unroll
        for (int p = 0; p < 2; p++) {
            uint32_t r4[4];
            ldm_x4(r4, bbase + p * (16 * BSTRIDE * 2) + kt * 32);
            B2[2 * p][0] = r4[0];     B2[2 * p][1] = r4[1];
            B2[2 * p + 1][0] = r4[2]; B2[2 * p + 1][1] = r4[3];
        }
        #pragma unroll
        for (int mt = 0; mt < 2; mt++)
            #pragma unroll
            for (int nt = 0; nt < 4; nt++)
                mma_bf16(acc[mt][nt], Ah[mt], B2[nt]);     // xh * wh
        #pragma unroll
        for (int mt = 0; mt < 2; mt++)
            #pragma unroll
            for (int nt = 0; nt < 4; nt++)
                mma_bf16(acc[mt][nt], Al[mt], B2[nt]);     // xl * wh

        // B lo fragments (reuse regs)
        #pragma unroll
        for (int p = 0; p < 2; p++) {
            uint32_t r4[4];
            ldm_x4(r4, bbase + 2 * BHALF + p * (16 * BSTRIDE * 2) + kt * 32);
            B2[2 * p][0] = r4[0];     B2[2 * p][1] = r4[1];
            B2[2 * p + 1][0] = r4[2]; B2[2 * p + 1][1] = r4[3];
        }
        #pragma unroll
        for (int mt = 0; mt < 2; mt++)
            #pragma unroll
            for (int nt = 0; nt < 4; nt++)
                mma_bf16(acc[mt][nt], Ah[mt], B2[nt]);     // xh * wl
    }

    // ---- epilogue: nt pairs (0,1)=(z,h) cols j=nhalf*16+2c+e, (2,3)=+8.
    //      W_lin partials are linear post-nonlinearity -> summable across n-halves.
    #pragma unroll
    for (int r = 0; r < 4; r++) {
        int mt = r >> 1;
        int eb = (r & 1) * 2;          // c0/c1 = row g, c2/c3 = row g+8
        float partial = 0.0f;
        #pragma unroll
        for (int p = 0; p < 2; p++) {
            #pragma unroll
            for (int e = 0; e < 2; e++) {
                int j = nhalf * 16 + p * 8 + 2 * c + e;
                float zv = acc[mt][2 * p][eb + e]     + __ldg(bz + j);
                float hv = acc[mt][2 * p + 1][eb + e] + __ldg(bh + j);
                float zz = sigmoid_f(zv);
                float ht = tanh_f(hv);
                partial = fmaf(fmaxf((1.0f - zz) * ht, 0.0f), __ldg(wlin + j), partial);
            }
        }
        partial += __shfl_xor_sync(0xffffffffu, partial, 1);
        partial += __shfl_xor_sync(0xffffffffu, partial, 2);
        if (c == 0) sRed[nhalf][mstrip * 32 + g + 8 * r] = partial;
    }
    __syncthreads();

    if (tid < TILE_M) {
        int grow = blockIdx.x * TILE_M + tid;
        if (grow < nNodes)
            out[grow] = sRed[0][tid] + sRed[1][tid] + __ldg(blin);
    }
}

// Inputs (metadata order):
// 0:x[N*128] f32   1:edge_index (dead)   2:edge_weight (dead)
// 3:W_z[10240]     4:b_z[32]   5:W_r (dead)   6:b_r (dead)
// 7:W_h[10240]     8:b_h[32]   9:W_lin[32]   10:b_lin[1]
extern "C" void kernel_launch(void* const* d_in, const int* in_sizes, int n_in,
                              void* d_out, int out_size) {
    const float* x     = (const float*)d_in[0];
    const float* W_z   = (const float*)d_in[3];
    const float* b_z   = (const float*)d_in[4];
    const float* W_h   = (const float*)d_in[7];
    const float* b_h   = (const float*)d_in[8];
    const float* W_lin = (const float*)d_in[9];
    const float* b_lin = (const float*)d_in[10];
    float* out = (float*)d_out;

    int nNodes = out_size;

    prep_kernel<<<(64 * 128 + 255) / 256, 256>>>(W_z, W_h);
    int blocks = (nNodes + TILE_M - 1) / TILE_M;
    dcrnn_mma_kernel<<<blocks, THREADS>>>(x, b_z, b_h, W_lin, b_lin, out, nNodes);
}

// round 10
// speedup vs baseline: 1.2364x; 1.2364x over previous
#include <cuda_runtime.h>
#include <cuda_bf16.h>
#include <cstdint>

#define HID     32
#define TILE_M  256
#define THREADS 256
#define BSTRIDE 136                  // padded bf16 per B row (272B): conflict-free ldmatrix
#define BHALF   (64 * BSTRIDE)       // elements per version (hi/lo)

#define APITCH   96                  // bytes per A row in smem ring (16 f32 + 32B pad)
#define ASTAGE   (32 * APITCH)       // 3072 B per stage per warp
#define ADEPTH   3
#define ARING    (8 * ADEPTH * ASTAGE)       // 73728 B
#define SB_OFF   ARING
#define SMEM_DYN (ARING + 2 * BHALF * 2)     // + 34816 B = 108544

// Fused W^T, split bf16: [hi: 64 rows x 136][lo: same], row n = output col, k contiguous.
__device__ __align__(16) __nv_bfloat16 g_B[2 * BHALF];

// W tensors shape (2,1,160,32); [s,0,k,j] = s*5120 + k*32 + j; only k<128 live (H0=0).
// B[n][k]: n<32 -> z gate col n, n>=32 -> h gate col n-32.
__global__ void prep_kernel(const float* __restrict__ Wz, const float* __restrict__ Wh) {
    int idx = blockIdx.x * blockDim.x + threadIdx.x;   // 0..8191
    if (idx >= 64 * 128) return;
    int n = idx >> 7;
    int k = idx & 127;
    int j = n & 31;
    const float* W = (n < 32) ? Wz : Wh;
    float v = W[k * 32 + j] + W[5120 + k * 32 + j];
    __nv_bfloat16 hi = __float2bfloat16_rn(v);
    float lo = v - __bfloat162float(hi);
    g_B[n * BSTRIDE + k]         = hi;
    g_B[BHALF + n * BSTRIDE + k] = __float2bfloat16_rn(lo);
}

// ---------------- helpers ----------------
__device__ __forceinline__ uint32_t smem_u32(const void* p) {
    uint32_t a;
    asm("{ .reg .u64 t; cvta.to.shared.u64 t, %1; cvt.u32.u64 %0, t; }" : "=r"(a) : "l"(p));
    return a;
}
__device__ __forceinline__ void mma_bf16(float* d, const uint32_t* a, const uint32_t* b) {
    asm volatile(
        "mma.sync.aligned.m16n8k16.row.col.f32.bf16.bf16.f32 "
        "{%0,%1,%2,%3}, {%4,%5,%6,%7}, {%8,%9}, {%0,%1,%2,%3};"
        : "+f"(d[0]), "+f"(d[1]), "+f"(d[2]), "+f"(d[3])
        : "r"(a[0]), "r"(a[1]), "r"(a[2]), "r"(a[3]), "r"(b[0]), "r"(b[1]));
}
__device__ __forceinline__ void ldm_x4(uint32_t* r, uint32_t addr) {
    asm volatile("ldmatrix.sync.aligned.m8n8.x4.shared.b16 {%0,%1,%2,%3}, [%4];"
        : "=r"(r[0]), "=r"(r[1]), "=r"(r[2]), "=r"(r[3]) : "r"(addr));
}
__device__ __forceinline__ void cpasync16(uint32_t dst, const void* src) {
    asm volatile("cp.async.cg.shared.global [%0], [%1], 16;" :: "r"(dst), "l"(src));
}
__device__ __forceinline__ void cp_commit() {
    asm volatile("cp.async.commit_group;" ::: "memory");
}
__device__ __forceinline__ void cp_wait2() {
    asm volatile("cp.async.wait_group 2;" ::: "memory");
}
__device__ __forceinline__ uint32_t pack_bf2(float a, float b) {
    __nv_bfloat162 t = __floats2bfloat162_rn(a, b);
    return *(uint32_t*)&t;
}
__device__ __forceinline__ float sigmoid_f(float v) {
    return __fdividef(1.0f, 1.0f + __expf(-v));
}
__device__ __forceinline__ float tanh_f(float v) {
    return 1.0f - __fdividef(2.0f, __expf(2.0f * v) + 1.0f);
}

__global__ void __launch_bounds__(THREADS, 2)
dcrnn_mma_kernel(const float* __restrict__ x,
                 const float* __restrict__ bz, const float* __restrict__ bh,
                 const float* __restrict__ wlin, const float* __restrict__ blin,
                 float* __restrict__ out, int nNodes)
{
    extern __shared__ __align__(16) unsigned char dsm[];
    unsigned char* smA = dsm;                 // A ring: warp w stage s at w*ADEPTH*ASTAGE + s*ASTAGE
    __nv_bfloat16*  sB = (__nv_bfloat16*)(dsm + SB_OFF);

    const int tid = threadIdx.x;

    // stage B (hi+lo) -> smem, 2176 uint4
    {
        const uint4* src = (const uint4*)g_B;
        uint4*       dst = (uint4*)sB;
        #pragma unroll
        for (int i = 0; i < 2176 / THREADS + 1; i++) {
            int e = tid + i * THREADS;
            if (e < 2176) dst[e] = src[e];
        }
    }
    __syncthreads();

    const int warp = tid >> 5;
    const int lane = tid & 31;
    const int g    = lane >> 2;        // 0..7
    const int c    = lane & 3;         // 0..3
    const int r8   = lane >> 2;        // async row-in-octet (same as g)
    const int ch   = lane & 3;         // async 16B chunk
    const int rowBase = blockIdx.x * TILE_M + warp * 32;

    const uint32_t warpRing = smem_u32(smA) + (uint32_t)(warp * ADEPTH * ASTAGE);

    // ---- async producer: stage 'st' <- A rows for k-tile kt ----
    auto issueA = [&](int kt, int st) {
        uint32_t dstBase = warpRing + (uint32_t)(st * ASTAGE);
        #pragma unroll
        for (int j = 0; j < 4; j++) {
            int lrow = j * 8 + r8;
            int grow = rowBase + lrow;
            if (grow >= nNodes) grow = nNodes - 1;
            const void* src = x + (size_t)grow * 128 + kt * 16 + ch * 4;
            cpasync16(dstBase + (uint32_t)(lrow * APITCH + ch * 16), src);
        }
    };

    // prologue: stages 0,1,2 <- kt 0,1,2
    issueA(0, 0); cp_commit();
    issueA(1, 1); cp_commit();
    issueA(2, 2); cp_commit();

    // B ldmatrix per-thread address component:
    // tgrp = lane>>3: 0:(n=trow,kb0) 1:(n=trow,kb1) 2:(n=8+trow,kb0) 3:(n=8+trow,kb1)
    const uint32_t sB0 = smem_u32(sB);
    const uint32_t tb  = (uint32_t)((((lane >> 4) << 3) + (lane & 7)) * (BSTRIDE * 2)
                                    + ((lane >> 3) & 1) * 16);
    const uint32_t bbase = sB0 + tb;

    float acc[2][8][4];
    #pragma unroll
    for (int mt = 0; mt < 2; mt++)
        #pragma unroll
        for (int nt = 0; nt < 8; nt++)
            #pragma unroll
            for (int e = 0; e < 4; e++) acc[mt][nt][e] = 0.0f;

    int scur = 0;
    #pragma unroll 1
    for (int kt = 0; kt < 8; kt++) {
        cp_wait2();              // group kt complete (<=2 pending)
        __syncwarp();

        // consume stage scur: fragment LDS.64 (conflict-free, 12g+c bijective) + split
        unsigned char* stp = smA + warp * ADEPTH * ASTAGE + scur * ASTAGE;
        uint32_t Ah[2][4], Al[2][4];
        #pragma unroll
        for (int mt = 0; mt < 2; mt++) {
            int r0 = g + 16 * mt;
            int r1 = g + 8 + 16 * mt;
            float2 f0 = *(const float2*)(stp + r0 * APITCH + 8 * c);        // cols 2c,2c+1
            float2 f1 = *(const float2*)(stp + r1 * APITCH + 8 * c);
            float2 f2 = *(const float2*)(stp + r0 * APITCH + 32 + 8 * c);   // cols 8+2c
            float2 f3 = *(const float2*)(stp + r1 * APITCH + 32 + 8 * c);
            float2 fv[4] = {f0, f1, f2, f3};
            #pragma unroll
            for (int q = 0; q < 4; q++) {
                __nv_bfloat162 h2 = __floats2bfloat162_rn(fv[q].x, fv[q].y);
                float lx = fv[q].x - __bfloat162float(h2.x);
                float ly = fv[q].y - __bfloat162float(h2.y);
                Ah[mt][q] = *(uint32_t*)&h2;
                Al[mt][q] = pack_bf2(lx, ly);
            }
        }

        // refill: stage scur <- kt+3 (async write lands long after the LDS above)
        if (kt + 3 < 8) issueA(kt + 3, scur);
        cp_commit();             // empty group when nothing issued keeps counting uniform

        // B hi fragments: 4x ldmatrix.x4 covering 8 n-tiles
        uint32_t B2[8][2];
        #pragma unroll
        for (int p = 0; p < 8; p += 2) {
            uint32_t r4[4];
            ldm_x4(r4, bbase + p * (8 * BSTRIDE * 2) + kt * 32);
            B2[p][0] = r4[0]; B2[p][1] = r4[1];
            B2[p + 1][0] = r4[2]; B2[p + 1][1] = r4[3];
        }
        #pragma unroll
        for (int mt = 0; mt < 2; mt++)
            #pragma unroll
            for (int nt = 0; nt < 8; nt++)
                mma_bf16(acc[mt][nt], Ah[mt], B2[nt]);     // xh * wh
        #pragma unroll
        for (int mt = 0; mt < 2; mt++)
            #pragma unroll
            for (int nt = 0; nt < 8; nt++)
                mma_bf16(acc[mt][nt], Al[mt], B2[nt]);     // xl * wh

        // B lo fragments (reuse regs)
        #pragma unroll
        for (int p = 0; p < 8; p += 2) {
            uint32_t r4[4];
            ldm_x4(r4, bbase + 2 * BHALF + p * (8 * BSTRIDE * 2) + kt * 32);
            B2[p][0] = r4[0]; B2[p][1] = r4[1];
            B2[p + 1][0] = r4[2]; B2[p + 1][1] = r4[3];
        }
        #pragma unroll
        for (int mt = 0; mt < 2; mt++)
            #pragma unroll
            for (int nt = 0; nt < 8; nt++)
                mma_bf16(acc[mt][nt], Ah[mt], B2[nt]);     // xh * wl

        scur = (scur == ADEPTH - 1) ? 0 : scur + 1;
    }

    // ---- epilogue: z at col j (n-tiles 0..3), h at col j+32 (n-tiles 4..7),
    //      both owned by the same thread. Quad shfl-reduce, lane c==0 stores.
    float bl = __ldg(blin);
    #pragma unroll
    for (int r = 0; r < 4; r++) {
        int mt = r >> 1;
        int eb = (r & 1) * 2;          // c0/c1 = row g, c2/c3 = row g+8
        float partial = 0.0f;
        #pragma unroll
        for (int ntz = 0; ntz < 4; ntz++) {
            #pragma unroll
            for (int e = 0; e < 2; e++) {
                int j = ntz * 8 + 2 * c + e;
                float zv = acc[mt][ntz][eb + e]     + __ldg(bz + j);
                float hv = acc[mt][ntz + 4][eb + e] + __ldg(bh + j);
                float zz = sigmoid_f(zv);
                float ht = tanh_f(hv);
                partial = fmaf(fmaxf((1.0f - zz) * ht, 0.0f), __ldg(wlin + j), partial);
            }
        }
        partial += __shfl_xor_sync(0xffffffffu, partial, 1);
        partial += __shfl_xor_sync(0xffffffffu, partial, 2);
        if (c == 0) {
            int grow = rowBase + g + 8 * r;
            if (grow < nNodes) out[grow] = partial + bl;
        }
    }
}

// Inputs (metadata order):
// 0:x[N*128] f32   1:edge_index (dead)   2:edge_weight (dead)
// 3:W_z[10240]     4:b_z[32]   5:W_r (dead)   6:b_r (dead)
// 7:W_h[10240]     8:b_h[32]   9:W_lin[32]   10:b_lin[1]
extern "C" void kernel_launch(void* const* d_in, const int* in_sizes, int n_in,
                              void* d_out, int out_size) {
    const float* x     = (const float*)d_in[0];
    const float* W_z   = (const float*)d_in[3];
    const float* b_z   = (const float*)d_in[4];
    const float* W_h   = (const float*)d_in[7];
    const float* b_h   = (const float*)d_in[8];
    const float* W_lin = (const float*)d_in[9];
    const float* b_lin = (const float*)d_in[10];
    float* out = (float*)d_out;

    int nNodes = out_size;

    // Idempotent, every call (no static guards per harness rules)
    cudaFuncSetAttribute(dcrnn_mma_kernel,
                         cudaFuncAttributeMaxDynamicSharedMemorySize, SMEM_DYN);

    prep_kernel<<<(64 * 128 + 255) / 256, 256>>>(W_z, W_h);
    int blocks = (nNodes + TILE_M - 1) / TILE_M;
    dcrnn_mma_kernel<<<blocks, THREADS, SMEM_DYN>>>(x, b_z, b_h, W_lin, b_lin,
                                                    out, nNodes);
}